// round 15
// baseline (speedup 1.0000x reference)
#include <cuda_runtime.h>
#include <cuda_bf16.h>
#include <math_constants.h>

#define B 8
#define N 65536
#define C 80
#define T 32
#define MIN_POS 16
#define POSKEY 0x3F000000u   // bits of 0.5f; IoU >= 0 so uint order == float order
#define CH 32                // chunks per image
#define CHK (N / CH)         // 2048 keys per chunk

// ---------------- scratch (device globals; zero-initialized, no allocation) ----
__device__ float    g_maxiou[B * N];
__device__ int      g_maxidx[B * N];
__device__ float    g_sl1[B * N];
__device__ int      g_hist1[B][4096];        // level-1: key>>20 (built in iou)
__device__ int      g_h2[B][2][4096];        // level-2: (key>>8)&0xFFF
__device__ int      g_h3[B][2][256];         // level-3 merged
__device__ int      g_h3c[B][CH][2][256];    // level-3 per-chunk (full store)
__device__ int      g_ctl[B][12];
__device__ float    g_clspos[B], g_clsneg[B], g_regsum[B];
__device__ int      g_done;

// ---------------- helpers ----------------
template <int BINS, int NT>
__device__ __forceinline__ void select_digit(const int* __restrict__ h, int kk,
                                             int tid, int lane, int wid,
                                             int* warp_sums, int* sh_out)
{
    constexpr int V = (BINS + NT - 1) / NT;
    constexpr int NW = NT / 32;
    int loc[V]; int tot = 0;
#pragma unroll
    for (int j = 0; j < V; j++) {
        int bin = tid * V + j;
        loc[j] = (bin < BINS) ? h[bin] : 0;
        tot += loc[j];
    }
    int v = tot;                                   // inclusive suffix within warp
#pragma unroll
    for (int o = 1; o < 32; o <<= 1) {
        int t = __shfl_down_sync(0xffffffffu, v, o);
        if (lane + o < 32) v += t;
    }
    __syncthreads();
    if (lane == 0) warp_sums[wid] = v;
    __syncthreads();
    if (wid == 0) {
        int w = (lane < NW) ? warp_sums[lane] : 0;
#pragma unroll
        for (int o = 1; o < 32; o <<= 1) {
            int t = __shfl_down_sync(0xffffffffu, w, o);
            if (lane + o < 32) w += t;
        }
        if (lane < NW) warp_sums[lane] = w;
    }
    __syncthreads();
    int base = ((wid + 1 < NW) ? warp_sums[wid + 1] : 0) + (v - tot);
    int s = base;
#pragma unroll
    for (int j = V - 1; j >= 0; j--) {
        int sa = s; s += loc[j];
        if (s >= kk && sa < kk) { sh_out[0] = tid * V + j; sh_out[1] = kk - sa; }
    }
    __syncthreads();
}

// Single-warp 256-bin select: each lane owns 8 bins. No block barriers.
// Writes {bin, kk - #greater} to sh_out[0..1].
__device__ __forceinline__ void warp_select256(const int* __restrict__ h, int kk,
                                               int lane, int* sh_out)
{
    int loc[8]; int tot = 0;
#pragma unroll
    for (int j = 0; j < 8; j++) { loc[j] = h[lane * 8 + j]; tot += loc[j]; }
    int v = tot;                                   // inclusive suffix across lanes
#pragma unroll
    for (int o = 1; o < 32; o <<= 1) {
        int t = __shfl_down_sync(0xffffffffu, v, o);
        if (lane + o < 32) v += t;
    }
    int base = v - tot;                            // sum over lanes > this lane... 
    // v = sum over lanes >= lane of tot; base = exclusive (lanes > lane)
    int s = base;
#pragma unroll
    for (int j = 7; j >= 0; j--) {
        int sa = s; s += loc[j];
        if (s >= kk && sa < kk) { sh_out[0] = lane * 8 + j; sh_out[1] = kk - sa; }
    }
}

template <int NW>
__device__ __forceinline__ int block_exscan(int v, int lane, int wid, int* warp_sums)
{
    __syncthreads();
    int inc = v;
#pragma unroll
    for (int o = 1; o < 32; o <<= 1) {
        int t = __shfl_up_sync(0xffffffffu, inc, o);
        if (lane >= o) inc += t;
    }
    if (lane == 31) warp_sums[wid] = inc;
    __syncthreads();
    if (wid == 0) {
        int w = (lane < NW) ? warp_sums[lane] : 0;
#pragma unroll
        for (int o = 1; o < 32; o <<= 1) {
            int t = __shfl_up_sync(0xffffffffu, w, o);
            if (lane >= o) w += t;
        }
        if (lane < NW) warp_sums[lane] = w;
    }
    __syncthreads();
    int base = wid ? warp_sums[wid - 1] : 0;
    return base + inc - v;
}

// ---------------- Kernel 1: decode + IoU (2/thread) + hist + smooth-L1 -------
__global__ __launch_bounds__(512) void iou_kernel(
    const float* __restrict__ reg, const float* __restrict__ anchors,
    const float* __restrict__ tboxes)
{
    __shared__ float4 sBox[T];
    __shared__ float  sAB[T];
    __shared__ int    sh[4096];

    int b = blockIdx.x >> 6;                  // 64 blocks/image, 1024 anchors each
    int n0 = ((blockIdx.x & 63) << 10) + threadIdx.x * 2;
    size_t gbase = (size_t)b * N;

    if (threadIdx.x < T) {
        float4 tb = ((const float4*)tboxes)[b * T + threadIdx.x];
        sBox[threadIdx.x] = tb;
        sAB[threadIdx.x] = (tb.z - tb.x) * (tb.w - tb.y);
    }
    for (int j = threadIdx.x; j < 4096; j += 512) sh[j] = 0;
    __syncthreads();

    float X1[2], Y1[2], X2[2], Y2[2], AR[2], BI[2], BD[2];
    int BX[2];
#pragma unroll
    for (int c = 0; c < 2; c++) {
        float4 a = ((const float4*)anchors)[n0 + c];
        float4 r = ((const float4*)reg)[gbase + n0 + c];
        float aw = a.z - a.x, ah = a.w - a.y;
        float acx = a.x + 0.5f * aw, acy = a.y + 0.5f * ah;
        float cx = r.x * aw + acx, cy = r.y * ah + acy;
        float w = __expf(r.z) * aw, h = __expf(r.w) * ah;
        X1[c] = cx - 0.5f * w; Y1[c] = cy - 0.5f * h;
        X2[c] = cx + 0.5f * w; Y2[c] = cy + 0.5f * h;
        AR[c] = (X2[c] - X1[c]) * (Y2[c] - Y1[c]);
        BI[c] = 0.f; BD[c] = 1.f; BX[c] = 0;
    }
#pragma unroll 8
    for (int t = 0; t < T; t++) {
        float4 g = sBox[t];
        float ab = sAB[t];
#pragma unroll
        for (int c = 0; c < 2; c++) {
            float lx = fmaxf(X1[c], g.x), ly = fmaxf(Y1[c], g.y);
            float rx = fminf(X2[c], g.z), ry = fminf(Y2[c], g.w);
            float ww = fmaxf(rx - lx, 0.0f), hh = fmaxf(ry - ly, 0.0f);
            float inter = ww * hh;
            float denom = AR[c] + ab - inter + 1e-6f;
            if (inter * BD[c] > BI[c] * denom) { BI[c] = inter; BD[c] = denom; BX[c] = t; }
        }
    }
#pragma unroll
    for (int c = 0; c < 2; c++) {
        float iou = __fdividef(BI[c], BD[c]);
        size_t gi = gbase + n0 + c;
        g_maxiou[gi] = iou;
        g_maxidx[gi] = BX[c];
        float4 a = ((const float4*)anchors)[n0 + c];
        float4 r = ((const float4*)reg)[gi];
        float4 g = sBox[BX[c]];
        float aw = a.z - a.x, ah = a.w - a.y;
        float acx = a.x + 0.5f * aw, acy = a.y + 0.5f * ah;
        float gw_ = g.z - g.x, gh_ = g.w - g.y;
        float gcx = g.x + 0.5f * gw_, gcy = g.y + 0.5f * gh_;
        float t0 = __fdividef(gcx - acx, aw + 1e-6f);
        float t1 = __fdividef(gcy - acy, ah + 1e-6f);
        float t2 = __logf(__fdividef(gw_, aw + 1e-6f));
        float t3 = __logf(__fdividef(gh_, ah + 1e-6f));
        float d0 = fabsf(r.x - t0), d1 = fabsf(r.y - t1);
        float d2 = fabsf(r.z - t2), d3 = fabsf(r.w - t3);
        float sl = 0.f;
        sl += (d0 < 1.f) ? 0.5f * d0 * d0 : d0 - 0.5f;
        sl += (d1 < 1.f) ? 0.5f * d1 * d1 : d1 - 0.5f;
        sl += (d2 < 1.f) ? 0.5f * d2 * d2 : d2 - 0.5f;
        sl += (d3 < 1.f) ? 0.5f * d3 * d3 : d3 - 0.5f;
        g_sl1[gi] = sl;
        atomicAdd(&sh[__float_as_uint(iou) >> 20], 1);
    }
    __syncthreads();
    for (int j = threadIdx.x; j < 4096; j += 512) {
        int v = sh[j];
        if (v) atomicAdd(&g_hist1[b][j], v);
    }
}

// ---------------- Kernel 2: level-2 histogram pass (CH blocks / image) -------
__global__ __launch_bounds__(512) void pass1_kernel()
{
    int b = blockIdx.x / CH, p = blockIdx.x % CH;
    int tid = threadIdx.x, lane = tid & 31, wid = tid >> 5;
    __shared__ int sh[2][4096];
    __shared__ int warp_sums[32];
    __shared__ int s_out[2];
    __shared__ int s_pos;

    if (tid == 0) s_pos = 0;
    __syncthreads();
    {
        int possum = 0;
#pragma unroll
        for (int j = tid; j < 4096; j += 512)
            if (j >= 0x3F0) possum += g_hist1[b][j];
#pragma unroll
        for (int o = 16; o; o >>= 1) possum += __shfl_down_sync(0xffffffffu, possum, o);
        if (lane == 0 && possum) atomicAdd(&s_pos, possum);
    }
    __syncthreads();
    int poscount = s_pos;
    int fb = (poscount < MIN_POS);
    int num_pos = fb ? MIN_POS : poscount;
    int k = min(N - num_pos, 4 * num_pos);

    select_digit<4096, 512>(g_hist1[b], MIN_POS, tid, lane, wid, warp_sums, s_out);
    int d16 = s_out[0], rem16 = s_out[1];
    select_digit<4096, 512>(g_hist1[b], k + num_pos, tid, lane, wid, warp_sums, s_out);
    int dN = s_out[0], remN = s_out[1];

    if (p == 0) {
        if (tid == 0) {
            g_ctl[b][0] = fb;  g_ctl[b][1] = num_pos; g_ctl[b][2] = k;
            g_ctl[b][3] = d16; g_ctl[b][4] = rem16;
            g_ctl[b][5] = dN;  g_ctl[b][6] = remN;
            g_clspos[b] = 0.f; g_clsneg[b] = 0.f; g_regsum[b] = 0.f;
        }
        if (tid < 512) ((int*)g_h3[b])[tid] = 0;
    }

    for (int i = tid; i < 8192; i += 512) ((int*)sh)[i] = 0;
    __syncthreads();

    const unsigned* keys = (const unsigned*)(g_maxiou + (size_t)b * N);
    const uint4* K4 = ((const uint4*)keys) + p * (CHK / 4);
    {
        uint4 v = K4[tid];
        unsigned a4[4] = { v.x, v.y, v.z, v.w };
#pragma unroll
        for (int c = 0; c < 4; c++) {
            unsigned key = a4[c];
            int hi = (int)(key >> 20);
            if (hi == d16) atomicAdd(&sh[0][(key >> 8) & 0xFFF], 1);
            if (hi == dN)  atomicAdd(&sh[1][(key >> 8) & 0xFFF], 1);
        }
    }
    __syncthreads();
    for (int i = tid; i < 8192; i += 512) {
        int v = ((int*)sh)[i];
        if (v) atomicAdd(&((int*)g_h2[b])[i], v);
    }
}

// ---------------- Kernel 3: level-3 hist + g_hist1 clear ---------------------
__global__ __launch_bounds__(512) void pass2_kernel()
{
    int b = blockIdx.x / CH, p = blockIdx.x % CH;
    int tid = threadIdx.x, lane = tid & 31, wid = tid >> 5;
    __shared__ int sh[2][256];
    __shared__ int warp_sums[32];
    __shared__ int s_out[2];

    int d16 = g_ctl[b][3], rem16 = g_ctl[b][4];
    int dN  = g_ctl[b][5], remN  = g_ctl[b][6];

    // clear g_hist1 for the next call (read finished in pass1)
    {
        int gid = blockIdx.x * 512 + tid;
        int stride = (B * CH) * 512;
        for (int i = gid; i < B * 4096; i += stride) ((int*)g_hist1)[i] = 0;
    }

    select_digit<4096, 512>(g_h2[b][0], rem16, tid, lane, wid, warp_sums, s_out);
    int p24_16 = (d16 << 12) | s_out[0]; int rem2_16 = s_out[1];
    select_digit<4096, 512>(g_h2[b][1], remN, tid, lane, wid, warp_sums, s_out);
    int p24_N = (dN << 12) | s_out[0]; int rem2_N = s_out[1];

    if (p == 0 && tid == 0) {
        g_ctl[b][7] = p24_16; g_ctl[b][8] = rem2_16;
        g_ctl[b][9] = p24_N;  g_ctl[b][10] = rem2_N;
    }

    if (tid < 512) ((int*)sh)[tid] = 0;
    __syncthreads();

    const unsigned* keys = (const unsigned*)(g_maxiou + (size_t)b * N);
    const uint4* K4 = ((const uint4*)keys) + p * (CHK / 4);
    {
        uint4 v = K4[tid];
        unsigned a4[4] = { v.x, v.y, v.z, v.w };
#pragma unroll
        for (int c = 0; c < 4; c++) {
            unsigned key = a4[c];
            int hi = (int)(key >> 8);
            if (hi == p24_16) atomicAdd(&sh[0][key & 0xFF], 1);
            if (hi == p24_N)  atomicAdd(&sh[1][key & 0xFF], 1);
        }
    }
    __syncthreads();
    if (tid < 512) {
        int v = ((int*)sh)[tid];
        ((int*)g_h3c[b][p])[tid] = v;
        if (v) atomicAdd(&((int*)g_h3[b])[tid], v);
    }
}

// ---------------- Kernel 4: fused tau + selection + loss + final -------------
__global__ __launch_bounds__(1024, 2) void loss_kernel(
    const float* __restrict__ cls, const int* __restrict__ tlabels,
    float* __restrict__ out)
{
    int b = blockIdx.x / CH, p = blockIdx.x % CH;
    int tid = threadIdx.x, lane = tid & 31, wid = tid >> 5;
    __shared__ int warp_sums[32];
    __shared__ int s_out16[2];
    __shared__ int s_outN[2];
    __shared__ unsigned s_list[CHK];
    __shared__ int s_lab[T];
    __shared__ int s_cnt;
    __shared__ int s_pre[2];
    __shared__ float s_acc[3];

    if (tid == 0) s_cnt = 0;
    if (tid < 3) s_acc[tid] = 0.f;
    if (tid < T) s_lab[tid] = tlabels[b * T + tid];

    // clear g_h2 for the next call
    {
        int gid = blockIdx.x * 1024 + tid;
        int stride = (B * CH) * 1024;
        for (int i = gid; i < B * 2 * 4096; i += stride) ((int*)g_h2)[i] = 0;
    }

    int fb = g_ctl[b][0];

    // warp-parallel 256-bin selects: warp 0 -> tau16, warp 1 -> tauN
    if (wid == 0) warp_select256(g_h3[b][0], g_ctl[b][8], lane, s_out16);
    if (wid == 1) warp_select256(g_h3[b][1], g_ctl[b][10], lane, s_outN);
    // chunk-level tie-rank prefixes need lb16/lbN -> after one barrier
    __syncthreads();
    int lb16 = s_out16[0], m16 = s_out16[1];
    unsigned tau16 = ((unsigned)g_ctl[b][7] << 8) | (unsigned)lb16;
    int lbN = s_outN[0], mN = s_outN[1];
    unsigned tauN = ((unsigned)g_ctl[b][9] << 8) | (unsigned)lbN;

    if (wid == 0) {
        int v16 = (lane < p && fb) ? g_h3c[b][lane][0][lb16] : 0;
        int vN  = (lane < p)       ? g_h3c[b][lane][1][lbN]  : 0;
#pragma unroll
        for (int o = 16; o; o >>= 1) {
            v16 += __shfl_down_sync(0xffffffffu, v16, o);
            vN  += __shfl_down_sync(0xffffffffu, vN, o);
        }
        if (lane == 0) { s_pre[0] = v16; s_pre[1] = vN; }
    }
    __syncthreads();
    int pre16 = s_pre[0], preN = s_pre[1];

    // ---- selection within this chunk (2 keys / thread, contiguous) ----
    const unsigned* keys = (const unsigned*)(g_maxiou + (size_t)b * N);
    uint2 v = ((const uint2*)keys)[p * (CHK / 2) + tid];
    unsigned a2[2] = { v.x, v.y };

    int r16 = 0;
    if (fb) {
        int c16 = (a2[0] == tau16) + (a2[1] == tau16);
        r16 = pre16 + block_exscan<32>(c16, lane, wid, warp_sums);
    }
    int cN = (a2[0] == tauN) + (a2[1] == tauN);
    int rN = preN + block_exscan<32>(cN, lane, wid, warp_sums);

    // decide pos/neg per key, then warp-aggregated append
    bool sel[2]; bool posf[2];
#pragma unroll
    for (int c = 0; c < 2; c++) {
        unsigned key = a2[c];
        bool eq16 = fb && (key == tau16);
        bool pos = fb ? (key > tau16 || (eq16 && r16 < m16)) : (key >= POSKEY);
        if (eq16) r16++;
        bool neg = false;
        if (!pos) {
            if (key > tauN) neg = true;
            else if (key == tauN) neg = (rN < mN);   // rank over ALL ties
        }
        if (key == tauN) rN++;
        sel[c] = pos | neg;
        posf[c] = pos;
    }
#pragma unroll
    for (int c = 0; c < 2; c++) {
        unsigned bal = __ballot_sync(0xffffffffu, sel[c]);
        int nsel = __popc(bal);
        int wbase = 0;
        if (lane == 0 && nsel) wbase = atomicAdd(&s_cnt, nsel);
        wbase = __shfl_sync(0xffffffffu, wbase, 0);
        if (sel[c]) {
            int off = __popc(bal & ((1u << lane) - 1u));
            unsigned idx = (unsigned)(p * CHK + tid * 2 + c);
            s_list[wbase + off] = idx | (posf[c] ? 0x80000000u : 0u);
        }
    }
    __syncthreads();
    int cnt = s_cnt;
    size_t gbase = (size_t)b * N;

    // ---- loss: 8-lane sub-warp groups, 5 float2 loads (R10 pattern) ----
    int g8 = lane >> 3;
    int sl = lane & 7;
    unsigned m8 = 0xFFu << (g8 * 8);
    float ap = 0.f, an = 0.f, ar = 0.f;
    for (int j = wid * 4 + g8; j < cnt; j += 128) {
        unsigned e = s_list[j];
        int ipos = (int)(e >> 31);
        int n = (int)(e & 0x7FFFFFFFu);
        size_t gi = gbase + n;
        const float2* row2 = (const float2*)(cls + gi * C);

        int mi = 0; float q = 0.f;
        if (sl == 0 && ipos) { mi = g_maxidx[gi]; q = g_sl1[gi]; }

        float2 f0 = row2[sl];
        float2 f1 = row2[sl + 8];
        float2 f2 = row2[sl + 16];
        float2 f3 = row2[sl + 24];
        float2 f4 = row2[sl + 32];
        float s = __expf(f0.x) + __expf(f0.y) + __expf(f1.x) + __expf(f1.y)
                + __expf(f2.x) + __expf(f2.y) + __expf(f3.x) + __expf(f3.y)
                + __expf(f4.x) + __expf(f4.y);
        s += __shfl_xor_sync(m8, s, 4);
        s += __shfl_xor_sync(m8, s, 2);
        s += __shfl_xor_sync(m8, s, 1);

        if (sl == 0) {
            float lse = __logf(s);
            if (ipos) {
                int lb = s_lab[mi];
                float ce = lse - (cls + gi * C)[lb];
                float pp = __expf(-ce), om = 1.f - pp;
                ap += 0.25f * om * om * ce;
                ar += q;
            } else {
                float ce = lse - f0.x;
                float pp = __expf(-ce), om = 1.f - pp;
                an += 0.9f * om * om * om * ce;
            }
        }
    }
    ap += __shfl_xor_sync(0xffffffffu, ap, 8);
    ap += __shfl_xor_sync(0xffffffffu, ap, 16);
    an += __shfl_xor_sync(0xffffffffu, an, 8);
    an += __shfl_xor_sync(0xffffffffu, an, 16);
    ar += __shfl_xor_sync(0xffffffffu, ar, 8);
    ar += __shfl_xor_sync(0xffffffffu, ar, 16);
    if (lane == 0 && (ap != 0.f || an != 0.f || ar != 0.f)) {
        atomicAdd(&s_acc[0], ap);
        atomicAdd(&s_acc[1], an);
        atomicAdd(&s_acc[2], ar);
    }
    __syncthreads();
    if (tid == 0 && s_acc[0] != 0.f) atomicAdd(&g_clspos[b], s_acc[0]);
    if (tid == 1 && s_acc[1] != 0.f) atomicAdd(&g_clsneg[b], s_acc[1]);
    if (tid == 2 && s_acc[2] != 0.f) atomicAdd(&g_regsum[b], s_acc[2]);
    __threadfence();
    __syncthreads();

    if (tid == 0) {
        int prev = atomicAdd(&g_done, 1);
        if (prev == (int)gridDim.x - 1) {
            float cls_sum = 0.f, reg_sum = 0.f;
            int tp = 0;
            for (int bb = 0; bb < B; bb++) {
                int np = g_ctl[bb][1], nn = g_ctl[bb][2];
                cls_sum += (g_clspos[bb] + g_clsneg[bb]) / (float)max(np + nn, 1);
                reg_sum += g_regsum[bb] / ((float)np + 1e-6f);
                tp += np;
            }
            float cls_final = cls_sum / (float)B;
            float reg_final = (tp > 0) ? (reg_sum / (float)B) : 0.f;
            float rw = fminf(1.f, (float)tp / (100.f * (float)B));
            out[0] = cls_final + rw * 1.0f * reg_final;
            out[1] = cls_final;
            out[2] = reg_final;
            out[3] = (float)tp;
            atomicExch(&g_done, 0);
        }
    }
}

// ---------------- launch ----------------
extern "C" void kernel_launch(void* const* d_in, const int* in_sizes, int n_in,
                              void* d_out, int out_size)
{
    const float* cls     = (const float*)d_in[0];
    const float* reg     = (const float*)d_in[1];
    const float* anchors = (const float*)d_in[2];
    const float* tboxes  = (const float*)d_in[3];
    const int*   tlabels = (const int*)d_in[4];
    float* out = (float*)d_out;

    iou_kernel<<<B * 64, 512>>>(reg, anchors, tboxes);
    pass1_kernel<<<B * CH, 512>>>();
    pass2_kernel<<<B * CH, 512>>>();
    loss_kernel<<<B * CH, 1024>>>(cls, tlabels, out);
}

// round 16
// speedup vs baseline: 1.5921x; 1.5921x over previous
#include <cuda_runtime.h>
#include <cuda_bf16.h>
#include <math_constants.h>

#define B 8
#define N 65536
#define C 80
#define T 32
#define MIN_POS 16
#define POSKEY 0x3F000000u   // bits of 0.5f; IoU >= 0 so uint order == float order
#define CH 32                // chunks per image
#define CHK (N / CH)         // 2048 keys per chunk

// ---------------- scratch (device globals; zero-initialized, no allocation) ----
__device__ float    g_maxiou[B * N];
__device__ int      g_maxidx[B * N];
__device__ float    g_sl1[B * N];            // precomputed smooth-L1 per anchor
__device__ int      g_hist1[B][4096];        // level-1: key>>20 (built in iou)
__device__ int      g_h2[B][2][4096];        // level-2: (key>>8)&0xFFF
__device__ int      g_h3[B][2][256];         // level-3 merged
__device__ int      g_h3c[B][CH][2][256];    // level-3 per-chunk (full store)
__device__ int      g_ctl[B][12];
__device__ float    g_clspos[B], g_clsneg[B], g_regsum[B];
__device__ int      g_done;

// ---------------- helpers ----------------
template <int BINS, int NT>
__device__ __forceinline__ void select_digit(const int* __restrict__ h, int kk,
                                             int tid, int lane, int wid,
                                             int* warp_sums, int* sh_out)
{
    constexpr int V = (BINS + NT - 1) / NT;
    constexpr int NW = NT / 32;
    int loc[V]; int tot = 0;
#pragma unroll
    for (int j = 0; j < V; j++) {
        int bin = tid * V + j;
        loc[j] = (bin < BINS) ? h[bin] : 0;
        tot += loc[j];
    }
    int v = tot;                                   // inclusive suffix within warp
#pragma unroll
    for (int o = 1; o < 32; o <<= 1) {
        int t = __shfl_down_sync(0xffffffffu, v, o);
        if (lane + o < 32) v += t;
    }
    __syncthreads();
    if (lane == 0) warp_sums[wid] = v;
    __syncthreads();
    if (wid == 0) {
        int w = (lane < NW) ? warp_sums[lane] : 0;
#pragma unroll
        for (int o = 1; o < 32; o <<= 1) {
            int t = __shfl_down_sync(0xffffffffu, w, o);
            if (lane + o < 32) w += t;
        }
        if (lane < NW) warp_sums[lane] = w;
    }
    __syncthreads();
    int base = ((wid + 1 < NW) ? warp_sums[wid + 1] : 0) + (v - tot);
    int s = base;
#pragma unroll
    for (int j = V - 1; j >= 0; j--) {
        int sa = s; s += loc[j];
        if (s >= kk && sa < kk) { sh_out[0] = tid * V + j; sh_out[1] = kk - sa; }
    }
    __syncthreads();
}

// Single-warp 256-bin select: each lane owns 8 bins; no block barriers.
__device__ __forceinline__ void warp_select256(const int* __restrict__ h, int kk,
                                               int lane, int* sh_out)
{
    int loc[8]; int tot = 0;
#pragma unroll
    for (int j = 0; j < 8; j++) { loc[j] = h[lane * 8 + j]; tot += loc[j]; }
    int v = tot;                                   // inclusive suffix across lanes
#pragma unroll
    for (int o = 1; o < 32; o <<= 1) {
        int t = __shfl_down_sync(0xffffffffu, v, o);
        if (lane + o < 32) v += t;
    }
    int s = v - tot;                               // exclusive: lanes > this lane
#pragma unroll
    for (int j = 7; j >= 0; j--) {
        int sa = s; s += loc[j];
        if (s >= kk && sa < kk) { sh_out[0] = lane * 8 + j; sh_out[1] = kk - sa; }
    }
}

template <int NW>
__device__ __forceinline__ int block_exscan(int v, int lane, int wid, int* warp_sums)
{
    __syncthreads();
    int inc = v;
#pragma unroll
    for (int o = 1; o < 32; o <<= 1) {
        int t = __shfl_up_sync(0xffffffffu, inc, o);
        if (lane >= o) inc += t;
    }
    if (lane == 31) warp_sums[wid] = inc;
    __syncthreads();
    if (wid == 0) {
        int w = (lane < NW) ? warp_sums[lane] : 0;
#pragma unroll
        for (int o = 1; o < 32; o <<= 1) {
            int t = __shfl_up_sync(0xffffffffu, w, o);
            if (lane >= o) w += t;
        }
        if (lane < NW) warp_sums[lane] = w;
    }
    __syncthreads();
    int base = wid ? warp_sums[wid - 1] : 0;
    return base + inc - v;
}

// ---------------- Kernel 1: decode + IoU + level-1 hist + smooth-L1 ----------
__global__ __launch_bounds__(256) void iou_kernel(
    const float* __restrict__ reg, const float* __restrict__ anchors,
    const float* __restrict__ tboxes)
{
    __shared__ float4 sBox[T];
    __shared__ float  sAB[T];
    __shared__ int    sh[4096];

    int b = blockIdx.x >> 8;
    int n = ((blockIdx.x & 255) << 8) + threadIdx.x;

    if (threadIdx.x < T) {
        float4 tb = ((const float4*)tboxes)[b * T + threadIdx.x];
        sBox[threadIdx.x] = tb;
        sAB[threadIdx.x] = (tb.z - tb.x) * (tb.w - tb.y);
    }
#pragma unroll
    for (int j = threadIdx.x; j < 4096; j += 256) sh[j] = 0;
    __syncthreads();

    float4 a = ((const float4*)anchors)[n];
    float4 r = ((const float4*)reg)[(size_t)b * N + n];

    float aw = a.z - a.x, ah = a.w - a.y;
    float acx = a.x + 0.5f * aw, acy = a.y + 0.5f * ah;
    float cx = r.x * aw + acx, cy = r.y * ah + acy;
    float w = __expf(r.z) * aw, h = __expf(r.w) * ah;
    float x1 = cx - 0.5f * w, y1 = cy - 0.5f * h;
    float x2 = cx + 0.5f * w, y2 = cy + 0.5f * h;
    float areaA = (x2 - x1) * (y2 - y1);

    float bi = 0.0f, bd = 1.0f;
    int bidx = 0;
#pragma unroll
    for (int t = 0; t < T; t++) {
        float4 g = sBox[t];
        float lx = fmaxf(x1, g.x), ly = fmaxf(y1, g.y);
        float rx = fminf(x2, g.z), ry = fminf(y2, g.w);
        float ww = fmaxf(rx - lx, 0.0f), hh = fmaxf(ry - ly, 0.0f);
        float inter = ww * hh;
        float denom = areaA + sAB[t] - inter + 1e-6f;
        if (inter * bd > bi * denom) { bi = inter; bd = denom; bidx = t; }
    }
    float iou = __fdividef(bi, bd);
    size_t gi = (size_t)b * N + n;
    g_maxiou[gi] = iou;
    g_maxidx[gi] = bidx;

    {
        float4 g = sBox[bidx];
        float gw_ = g.z - g.x, gh_ = g.w - g.y;
        float gcx = g.x + 0.5f * gw_, gcy = g.y + 0.5f * gh_;
        float t0 = __fdividef(gcx - acx, aw + 1e-6f);
        float t1 = __fdividef(gcy - acy, ah + 1e-6f);
        float t2 = __logf(__fdividef(gw_, aw + 1e-6f));
        float t3 = __logf(__fdividef(gh_, ah + 1e-6f));
        float d0 = fabsf(r.x - t0), d1 = fabsf(r.y - t1);
        float d2 = fabsf(r.z - t2), d3 = fabsf(r.w - t3);
        float sl = 0.f;
        sl += (d0 < 1.f) ? 0.5f * d0 * d0 : d0 - 0.5f;
        sl += (d1 < 1.f) ? 0.5f * d1 * d1 : d1 - 0.5f;
        sl += (d2 < 1.f) ? 0.5f * d2 * d2 : d2 - 0.5f;
        sl += (d3 < 1.f) ? 0.5f * d3 * d3 : d3 - 0.5f;
        g_sl1[gi] = sl;
    }

    atomicAdd(&sh[__float_as_uint(iou) >> 20], 1);
    __syncthreads();
#pragma unroll
    for (int j = threadIdx.x; j < 4096; j += 256) {
        int v = sh[j];
        if (v) atomicAdd(&g_hist1[b][j], v);
    }
}

// ---------------- Kernel 2: level-2 histogram pass (CH blocks / image) -------
__global__ __launch_bounds__(512) void pass1_kernel()
{
    int b = blockIdx.x / CH, p = blockIdx.x % CH;
    int tid = threadIdx.x, lane = tid & 31, wid = tid >> 5;
    __shared__ int sh[2][4096];
    __shared__ int warp_sums[32];
    __shared__ int s_out[2];
    __shared__ int s_pos;

    if (tid == 0) s_pos = 0;
    __syncthreads();
    {
        int possum = 0;
#pragma unroll
        for (int j = tid; j < 4096; j += 512)
            if (j >= 0x3F0) possum += g_hist1[b][j];
#pragma unroll
        for (int o = 16; o; o >>= 1) possum += __shfl_down_sync(0xffffffffu, possum, o);
        if (lane == 0 && possum) atomicAdd(&s_pos, possum);
    }
    __syncthreads();
    int poscount = s_pos;
    int fb = (poscount < MIN_POS);
    int num_pos = fb ? MIN_POS : poscount;
    int k = min(N - num_pos, 4 * num_pos);

    select_digit<4096, 512>(g_hist1[b], MIN_POS, tid, lane, wid, warp_sums, s_out);
    int d16 = s_out[0], rem16 = s_out[1];
    select_digit<4096, 512>(g_hist1[b], k + num_pos, tid, lane, wid, warp_sums, s_out);
    int dN = s_out[0], remN = s_out[1];

    if (p == 0) {
        if (tid == 0) {
            g_ctl[b][0] = fb;  g_ctl[b][1] = num_pos; g_ctl[b][2] = k;
            g_ctl[b][3] = d16; g_ctl[b][4] = rem16;
            g_ctl[b][5] = dN;  g_ctl[b][6] = remN;
            g_clspos[b] = 0.f; g_clsneg[b] = 0.f; g_regsum[b] = 0.f;
        }
        if (tid < 512) ((int*)g_h3[b])[tid] = 0;
    }

    for (int i = tid; i < 8192; i += 512) ((int*)sh)[i] = 0;
    __syncthreads();

    const unsigned* keys = (const unsigned*)(g_maxiou + (size_t)b * N);
    const uint4* K4 = ((const uint4*)keys) + p * (CHK / 4);
    {
        uint4 v = K4[tid];
        unsigned a4[4] = { v.x, v.y, v.z, v.w };
#pragma unroll
        for (int c = 0; c < 4; c++) {
            unsigned key = a4[c];
            int hi = (int)(key >> 20);
            if (hi == d16) atomicAdd(&sh[0][(key >> 8) & 0xFFF], 1);
            if (hi == dN)  atomicAdd(&sh[1][(key >> 8) & 0xFFF], 1);
        }
    }
    __syncthreads();
    for (int i = tid; i < 8192; i += 512) {
        int v = ((int*)sh)[i];
        if (v) atomicAdd(&((int*)g_h2[b])[i], v);
    }
}

// ---------------- Kernel 3: level-3 hist (merged + per-chunk) ----------------
__global__ __launch_bounds__(512) void pass2_kernel()
{
    int b = blockIdx.x / CH, p = blockIdx.x % CH;
    int tid = threadIdx.x, lane = tid & 31, wid = tid >> 5;
    __shared__ int sh[2][256];
    __shared__ int warp_sums[32];
    __shared__ int s_out[2];

    int d16 = g_ctl[b][3], rem16 = g_ctl[b][4];
    int dN  = g_ctl[b][5], remN  = g_ctl[b][6];

    select_digit<4096, 512>(g_h2[b][0], rem16, tid, lane, wid, warp_sums, s_out);
    int p24_16 = (d16 << 12) | s_out[0]; int rem2_16 = s_out[1];
    select_digit<4096, 512>(g_h2[b][1], remN, tid, lane, wid, warp_sums, s_out);
    int p24_N = (dN << 12) | s_out[0]; int rem2_N = s_out[1];

    if (p == 0 && tid == 0) {
        g_ctl[b][7] = p24_16; g_ctl[b][8] = rem2_16;
        g_ctl[b][9] = p24_N;  g_ctl[b][10] = rem2_N;
    }

    if (tid < 512) ((int*)sh)[tid] = 0;
    __syncthreads();

    const unsigned* keys = (const unsigned*)(g_maxiou + (size_t)b * N);
    const uint4* K4 = ((const uint4*)keys) + p * (CHK / 4);
    {
        uint4 v = K4[tid];
        unsigned a4[4] = { v.x, v.y, v.z, v.w };
#pragma unroll
        for (int c = 0; c < 4; c++) {
            unsigned key = a4[c];
            int hi = (int)(key >> 8);
            if (hi == p24_16) atomicAdd(&sh[0][key & 0xFF], 1);
            if (hi == p24_N)  atomicAdd(&sh[1][key & 0xFF], 1);
        }
    }
    __syncthreads();
    if (tid < 512) {
        int v = ((int*)sh)[tid];
        ((int*)g_h3c[b][p])[tid] = v;
        if (v) atomicAdd(&((int*)g_h3[b])[tid], v);
    }
}

// ---------------- Kernel 4: fused tau + selection + loss + final -------------
__global__ __launch_bounds__(1024, 2) void loss_kernel(
    const float* __restrict__ cls, const int* __restrict__ tlabels,
    float* __restrict__ out)
{
    int b = blockIdx.x / CH, p = blockIdx.x % CH;
    int tid = threadIdx.x, lane = tid & 31, wid = tid >> 5;
    __shared__ int warp_sums[32];
    __shared__ int s_out16[2];
    __shared__ int s_outN[2];
    __shared__ unsigned s_list[CHK];
    __shared__ int s_lab[T];
    __shared__ int s_cnt;
    __shared__ int s_pre[2];
    __shared__ float s_acc[3];

    if (tid == 0) s_cnt = 0;
    if (tid < 3) s_acc[tid] = 0.f;
    if (tid < T) s_lab[tid] = tlabels[b * T + tid];

    // clear level-1/level-2 hists for the next call
    {
        int gid = blockIdx.x * 1024 + tid;
        int stride = (B * CH) * 1024;
        for (int i = gid; i < B * 4096; i += stride) ((int*)g_hist1)[i] = 0;
        for (int i = gid; i < B * 2 * 4096; i += stride) ((int*)g_h2)[i] = 0;
    }

    int fb = g_ctl[b][0];

    // warp-parallel 256-bin selects (replaces two block-wide select_digit)
    if (wid == 0) warp_select256(g_h3[b][0], g_ctl[b][8], lane, s_out16);
    if (wid == 1) warp_select256(g_h3[b][1], g_ctl[b][10], lane, s_outN);
    __syncthreads();
    int lb16 = s_out16[0], m16 = s_out16[1];
    unsigned tau16 = ((unsigned)g_ctl[b][7] << 8) | (unsigned)lb16;
    int lbN = s_outN[0], mN = s_outN[1];
    unsigned tauN = ((unsigned)g_ctl[b][9] << 8) | (unsigned)lbN;

    // chunk-level tie-rank prefixes
    if (wid == 0) {
        int v16 = (lane < p && fb) ? g_h3c[b][lane][0][lb16] : 0;
        int vN  = (lane < p)       ? g_h3c[b][lane][1][lbN]  : 0;
#pragma unroll
        for (int o = 16; o; o >>= 1) {
            v16 += __shfl_down_sync(0xffffffffu, v16, o);
            vN  += __shfl_down_sync(0xffffffffu, vN, o);
        }
        if (lane == 0) { s_pre[0] = v16; s_pre[1] = vN; }
    }
    __syncthreads();
    int pre16 = s_pre[0], preN = s_pre[1];

    // ---- selection within this chunk (2 keys / thread, contiguous) ----
    const unsigned* keys = (const unsigned*)(g_maxiou + (size_t)b * N);
    uint2 v = ((const uint2*)keys)[p * (CHK / 2) + tid];
    unsigned a2[2] = { v.x, v.y };

    int r16 = 0;
    if (fb) {
        int c16 = (a2[0] == tau16) + (a2[1] == tau16);
        r16 = pre16 + block_exscan<32>(c16, lane, wid, warp_sums);
    }
    int cN = (a2[0] == tauN) + (a2[1] == tauN);
    int rN = preN + block_exscan<32>(cN, lane, wid, warp_sums);

    // decide pos/neg per key, then warp-aggregated append
    bool sel[2]; bool posf[2];
#pragma unroll
    for (int c = 0; c < 2; c++) {
        unsigned key = a2[c];
        bool eq16 = fb && (key == tau16);
        bool pos = fb ? (key > tau16 || (eq16 && r16 < m16)) : (key >= POSKEY);
        if (eq16) r16++;
        bool neg = false;
        if (!pos) {
            if (key > tauN) neg = true;
            else if (key == tauN) neg = (rN < mN);   // rank over ALL ties
        }
        if (key == tauN) rN++;
        sel[c] = pos | neg;
        posf[c] = pos;
    }
#pragma unroll
    for (int c = 0; c < 2; c++) {
        unsigned bal = __ballot_sync(0xffffffffu, sel[c]);
        int nsel = __popc(bal);
        int wbase = 0;
        if (lane == 0 && nsel) wbase = atomicAdd(&s_cnt, nsel);
        wbase = __shfl_sync(0xffffffffu, wbase, 0);
        if (sel[c]) {
            int off = __popc(bal & ((1u << lane) - 1u));
            unsigned idx = (unsigned)(p * CHK + tid * 2 + c);
            s_list[wbase + off] = idx | (posf[c] ? 0x80000000u : 0u);
        }
    }
    __syncthreads();
    int cnt = s_cnt;
    size_t gbase = (size_t)b * N;

    // ---- loss: 8-lane sub-warp groups, 5 float2 loads (R10 pattern) ----
    int g8 = lane >> 3;
    int sl = lane & 7;
    unsigned m8 = 0xFFu << (g8 * 8);
    float ap = 0.f, an = 0.f, ar = 0.f;
    for (int j = wid * 4 + g8; j < cnt; j += 128) {
        unsigned e = s_list[j];
        int ipos = (int)(e >> 31);
        int n = (int)(e & 0x7FFFFFFFu);
        size_t gi = gbase + n;
        const float2* row2 = (const float2*)(cls + gi * C);

        int mi = 0; float q = 0.f;
        if (sl == 0 && ipos) { mi = g_maxidx[gi]; q = g_sl1[gi]; }

        float2 f0 = row2[sl];
        float2 f1 = row2[sl + 8];
        float2 f2 = row2[sl + 16];
        float2 f3 = row2[sl + 24];
        float2 f4 = row2[sl + 32];
        float s = __expf(f0.x) + __expf(f0.y) + __expf(f1.x) + __expf(f1.y)
                + __expf(f2.x) + __expf(f2.y) + __expf(f3.x) + __expf(f3.y)
                + __expf(f4.x) + __expf(f4.y);
        s += __shfl_xor_sync(m8, s, 4);
        s += __shfl_xor_sync(m8, s, 2);
        s += __shfl_xor_sync(m8, s, 1);

        if (sl == 0) {
            float lse = __logf(s);
            if (ipos) {
                int lb = s_lab[mi];
                float ce = lse - (cls + gi * C)[lb];
                float pp = __expf(-ce), om = 1.f - pp;
                ap += 0.25f * om * om * ce;
                ar += q;
            } else {
                float ce = lse - f0.x;
                float pp = __expf(-ce), om = 1.f - pp;
                an += 0.9f * om * om * om * ce;
            }
        }
    }
    ap += __shfl_xor_sync(0xffffffffu, ap, 8);
    ap += __shfl_xor_sync(0xffffffffu, ap, 16);
    an += __shfl_xor_sync(0xffffffffu, an, 8);
    an += __shfl_xor_sync(0xffffffffu, an, 16);
    ar += __shfl_xor_sync(0xffffffffu, ar, 8);
    ar += __shfl_xor_sync(0xffffffffu, ar, 16);
    if (lane == 0 && (ap != 0.f || an != 0.f || ar != 0.f)) {
        atomicAdd(&s_acc[0], ap);
        atomicAdd(&s_acc[1], an);
        atomicAdd(&s_acc[2], ar);
    }
    __syncthreads();
    if (tid == 0 && s_acc[0] != 0.f) atomicAdd(&g_clspos[b], s_acc[0]);
    if (tid == 1 && s_acc[1] != 0.f) atomicAdd(&g_clsneg[b], s_acc[1]);
    if (tid == 2 && s_acc[2] != 0.f) atomicAdd(&g_regsum[b], s_acc[2]);
    __threadfence();
    __syncthreads();

    if (tid == 0) {
        int prev = atomicAdd(&g_done, 1);
        if (prev == (int)gridDim.x - 1) {
            float cls_sum = 0.f, reg_sum = 0.f;
            int tp = 0;
            for (int bb = 0; bb < B; bb++) {
                int np = g_ctl[bb][1], nn = g_ctl[bb][2];
                cls_sum += (g_clspos[bb] + g_clsneg[bb]) / (float)max(np + nn, 1);
                reg_sum += g_regsum[bb] / ((float)np + 1e-6f);
                tp += np;
            }
            float cls_final = cls_sum / (float)B;
            float reg_final = (tp > 0) ? (reg_sum / (float)B) : 0.f;
            float rw = fminf(1.f, (float)tp / (100.f * (float)B));
            out[0] = cls_final + rw * 1.0f * reg_final;
            out[1] = cls_final;
            out[2] = reg_final;
            out[3] = (float)tp;
            atomicExch(&g_done, 0);
        }
    }
}

// ---------------- launch ----------------
extern "C" void kernel_launch(void* const* d_in, const int* in_sizes, int n_in,
                              void* d_out, int out_size)
{
    const float* cls     = (const float*)d_in[0];
    const float* reg     = (const float*)d_in[1];
    const float* anchors = (const float*)d_in[2];
    const float* tboxes  = (const float*)d_in[3];
    const int*   tlabels = (const int*)d_in[4];
    float* out = (float*)d_out;

    iou_kernel<<<B * (N / 256), 256>>>(reg, anchors, tboxes);
    pass1_kernel<<<B * CH, 512>>>();
    pass2_kernel<<<B * CH, 512>>>();
    loss_kernel<<<B * CH, 1024>>>(cls, tlabels, out);
}